// round 16
// baseline (speedup 1.0000x reference)
#include <cuda_runtime.h>
#include <cuda_bf16.h>
#include <math.h>

#define NN   50000
#define EE   800000
#define GG   512

// ---------------- scratch (static device globals; no allocation allowed) ----
// All accumulating arrays are zeroed by their LAST consumer each run, so the
// pipeline is self-cleaning across graph replays (and starts zeroed at load).
__device__ int    g_cnt[NN];
__device__ int    g_rowptr[NN + 1];
__device__ int    g_cursor[NN];
__device__ float4 g_edge[EE];          // {ea0, ea1, ea2, bitcast(src)} CSR-by-dst
__device__ __nv_bfloat162 g_xl1h[NN * 64];  // xl1 in bf16x2 (gathered per edge)
__device__ float  g_xr1[NN * 128];
__device__ float  g_h1[NN * 128];
__device__ __nv_bfloat162 g_xl2h[NN * 32];  // xl2 in bf16x2 (gathered per edge)
__device__ float  g_xr2[NN * 64];
__device__ float  g_pooled[GG * 64];
__device__ int    g_gcnt[GG];
__device__ int    g_bsum[64];

// ---------------- in-degree (int atomics only) -----------------------------
__global__ void k_degree(const int* __restrict__ ei) {
    int e = blockIdx.x * blockDim.x + threadIdx.x;
    if (e >= EE) return;
    atomicAdd(&g_cnt[ei[EE + e]], 1);
}

// ---------------- 2-phase multi-block exclusive scan of deg ----------------
// 64 blocks x 256 threads x 4 elems covers NN=50000
__global__ void k_scan1() {
    __shared__ int red[256];
    int t = threadIdx.x, b = blockIdx.x;
    int g = b * 256 + t;
    int s = 0;
#pragma unroll
    for (int i = 0; i < 4; i++) {
        int v = g * 4 + i;
        if (v < NN) s += g_cnt[v];
    }
    red[t] = s;
    __syncthreads();
    for (int off = 128; off > 0; off >>= 1) {
        if (t < off) red[t] += red[t + off];
        __syncthreads();
    }
    if (t == 0) g_bsum[b] = red[0];
}

__global__ void k_scan3() {
    __shared__ int wsum[8];
    __shared__ int boff_s;
    int t = threadIdx.x, b = blockIdx.x;
    int lane = t & 31, warp = t >> 5;
    if (t == 0) {
        int r = 0;
        for (int i = 0; i < b; i++) r += g_bsum[i];
        boff_s = r;
    }
    int g = b * 256 + t;
    int vals[4];
    int tot = 0;
#pragma unroll
    for (int i = 0; i < 4; i++) {
        int v = g * 4 + i;
        vals[i] = (v < NN) ? g_cnt[v] : 0;
        tot += vals[i];
    }
    int inc = tot;
#pragma unroll
    for (int off = 1; off < 32; off <<= 1) {
        int n = __shfl_up_sync(0xffffffffu, inc, off);
        if (lane >= off) inc += n;
    }
    if (lane == 31) wsum[warp] = inc;
    __syncthreads();
    if (t == 0) {
        int r = 0;
        for (int w = 0; w < 8; w++) { int x = wsum[w]; wsum[w] = r; r += x; }
    }
    __syncthreads();
    int run = boff_s + wsum[warp] + inc - tot;  // exclusive prefix
#pragma unroll
    for (int i = 0; i < 4; i++) {
        int v = g * 4 + i;
        if (v < NN) {
            g_rowptr[v] = run;
            g_cursor[v] = run;       // scatter bumps this directly
            g_cnt[v] = 0;            // self-clean for the next run
            run += vals[i];
            if (v == NN - 1) g_rowptr[NN] = run;
        }
    }
}

// ---------------- scatter edges (+attrs) into CSR-by-dst -------------------
__global__ void k_scatter(const int* __restrict__ ei, const float* __restrict__ ea) {
    int e = blockIdx.x * blockDim.x + threadIdx.x;
    if (e >= EE) return;
    int s = ei[e], d = ei[EE + e];
    int pos = atomicAdd(&g_cursor[d], 1);
    float4 q;
    q.x = ea[e * 3 + 0];
    q.y = ea[e * 3 + 1];
    q.z = ea[e * 3 + 2];
    q.w = __int_as_float(s);
    g_edge[pos] = q;
}

// ---------------- tf32 tensor-core GEMM (m16n8k4, static 28KB smem) --------
// blockIdx.z==0 -> xl output packed bf16x2 (gather table); z==1 -> xr fp32.
__device__ __forceinline__ unsigned f2tf32(float f) {
    unsigned r;
    asm("cvt.rna.tf32.f32 %0, %1;" : "=r"(r) : "f"(f));
    return r;
}

__device__ __forceinline__ void mma_k4(float c[4], unsigned a0, unsigned a1, unsigned b0) {
    asm volatile(
        "mma.sync.aligned.m16n8k4.row.col.f32.tf32.tf32.f32 "
        "{%0,%1,%2,%3}, {%4,%5}, {%6}, {%0,%1,%2,%3};"
        : "+f"(c[0]), "+f"(c[1]), "+f"(c[2]), "+f"(c[3])
        : "r"(a0), "r"(a1), "r"(b0));
}

__global__ void gemm_tf32(const float* __restrict__ A,
                          const float* __restrict__ W0, const float* __restrict__ W1,
                          const float* __restrict__ bias0, const float* __restrict__ bias1,
                          __nv_bfloat162* __restrict__ C0h, float* __restrict__ C1,
                          int M, int Ncol) {
    __shared__ unsigned Bh[64][36];
    __shared__ unsigned As[128][36];

    const float* W    = blockIdx.z ? W1 : W0;
    const float* bias = blockIdx.z ? bias1 : bias0;

    int tid = threadIdx.x;
    int lane = tid & 31, warp = tid >> 5;
    int bm = blockIdx.y * 128;
    int bn = blockIdx.x * 64;
    int wm = (warp & 3) * 32;
    int wn = (warp >> 2) * 32;
    int lr = lane >> 2;
    int lc = lane & 3;

    float c[2][4][4] = {};

    for (int k0 = 0; k0 < 128; k0 += 32) {
#pragma unroll
        for (int i = 0; i < 2; i++) {
            int idx = tid + i * 256;
            int n = idx >> 3;
            int c4 = (idx & 7) * 4;
            float4 wv = *(const float4*)&W[(size_t)(bn + n) * 128 + k0 + c4];
            Bh[n][c4 + 0] = f2tf32(wv.x);
            Bh[n][c4 + 1] = f2tf32(wv.y);
            Bh[n][c4 + 2] = f2tf32(wv.z);
            Bh[n][c4 + 3] = f2tf32(wv.w);
        }
#pragma unroll
        for (int i = 0; i < 4; i++) {
            int idx = tid + i * 256;
            int r = idx >> 3;
            int c4 = (idx & 7) * 4;
            float4 av = make_float4(0.f, 0.f, 0.f, 0.f);
            if (bm + r < M) av = *(const float4*)&A[(size_t)(bm + r) * 128 + k0 + c4];
            As[r][c4 + 0] = f2tf32(av.x);
            As[r][c4 + 1] = f2tf32(av.y);
            As[r][c4 + 2] = f2tf32(av.z);
            As[r][c4 + 3] = f2tf32(av.w);
        }
        __syncthreads();

#pragma unroll
        for (int kk = 0; kk < 32; kk += 4) {
            unsigned a0[2], a1[2], bh[4];
#pragma unroll
            for (int mt = 0; mt < 2; mt++) {
                int row = wm + mt * 16 + lr;
                a0[mt] = As[row][kk + lc];
                a1[mt] = As[row + 8][kk + lc];
            }
#pragma unroll
            for (int nt = 0; nt < 4; nt++) {
                int n = wn + nt * 8 + lr;
                bh[nt] = Bh[n][kk + lc];
            }
#pragma unroll
            for (int mt = 0; mt < 2; mt++)
#pragma unroll
                for (int nt = 0; nt < 4; nt++)
                    mma_k4(c[mt][nt], a0[mt], a1[mt], bh[nt]);
        }
        __syncthreads();
    }

    int half = Ncol >> 1;
#pragma unroll
    for (int mt = 0; mt < 2; mt++) {
#pragma unroll
        for (int nt = 0; nt < 4; nt++) {
            int r0 = bm + wm + mt * 16 + lr;
            int cc = bn + wn + nt * 8 + lc * 2;     // always even
            float b0v = bias[cc], b1v = bias[cc + 1];
            if (blockIdx.z == 0) {
                if (r0 < M)
                    C0h[(size_t)r0 * half + (cc >> 1)] =
                        __floats2bfloat162_rn(c[mt][nt][0] + b0v, c[mt][nt][1] + b1v);
                if (r0 + 8 < M)
                    C0h[(size_t)(r0 + 8) * half + (cc >> 1)] =
                        __floats2bfloat162_rn(c[mt][nt][2] + b0v, c[mt][nt][3] + b1v);
            } else {
                if (r0 < M) {
                    C1[(size_t)r0 * Ncol + cc]     = c[mt][nt][0] + b0v;
                    C1[(size_t)r0 * Ncol + cc + 1] = c[mt][nt][1] + b1v;
                }
                if (r0 + 8 < M) {
                    C1[(size_t)(r0 + 8) * Ncol + cc]     = c[mt][nt][2] + b0v;
                    C1[(size_t)(r0 + 8) * Ncol + cc + 1] = c[mt][nt][3] + b1v;
                }
            }
        }
    }
}

// ---------------- GATv2 layer 1: HALF-warp per node; lane owns 8 channels ---
// 16 lanes/node; head = 32ch = 4 lanes -> 2-shfl reduce within masked group.
// Plain exp-sum softmax (scores bounded); edges are independent sums.
__global__ void k_gat1(const float* __restrict__ We, const float* __restrict__ att,
                       const float* __restrict__ bias) {
    int gw = (blockIdx.x * blockDim.x + threadIdx.x) >> 5;
    int lane = threadIdx.x & 31;
    int half = lane >> 4, ln = lane & 15;
    int v = 2 * gw + half;
    if (v >= NN) return;
    unsigned hm = half ? 0xFFFF0000u : 0x0000FFFFu;
    int cb = 8 * ln;                     // first of 8 channels this lane owns
    float4 aA = *(const float4*)&att[cb];
    float4 aB = *(const float4*)&att[cb + 4];
    float w0[8], w1[8], w2[8];
#pragma unroll
    for (int j = 0; j < 8; j++) {
        w0[j] = We[(cb + j) * 3 + 0];
        w1[j] = We[(cb + j) * 3 + 1];
        w2[j] = We[(cb + j) * 3 + 2];
    }
    float4 xrA = *(const float4*)&g_xr1[(long)v * 128 + cb];
    float4 xrB = *(const float4*)&g_xr1[(long)v * 128 + cb + 4];
    float den = 0.f;
    float4 accA = make_float4(0.f, 0.f, 0.f, 0.f);
    float4 accB = make_float4(0.f, 0.f, 0.f, 0.f);
    int pbeg = g_rowptr[v], pend = g_rowptr[v + 1];
    float se0 = 0.f, se1 = 0.f, se2 = 0.f;
#pragma unroll 2
    for (int p = pbeg; p < pend; ++p) {
        float4 q = g_edge[p];
        int s = __float_as_int(q.w);
        se0 += q.x; se1 += q.y; se2 += q.z;
        uint4 raw = *(const uint4*)(g_xl1h + (long)s * 64 + 4 * ln);
        float2 p01 = __bfloat1622float2(*(__nv_bfloat162*)&raw.x);
        float2 p23 = __bfloat1622float2(*(__nv_bfloat162*)&raw.y);
        float2 p45 = __bfloat1622float2(*(__nv_bfloat162*)&raw.z);
        float2 p67 = __bfloat1622float2(*(__nv_bfloat162*)&raw.w);
        float m0 = p01.x + xrA.x + w0[0] * q.x + w1[0] * q.y + w2[0] * q.z;
        float m1 = p01.y + xrA.y + w0[1] * q.x + w1[1] * q.y + w2[1] * q.z;
        float m2 = p23.x + xrA.z + w0[2] * q.x + w1[2] * q.y + w2[2] * q.z;
        float m3 = p23.y + xrA.w + w0[3] * q.x + w1[3] * q.y + w2[3] * q.z;
        float m4 = p45.x + xrB.x + w0[4] * q.x + w1[4] * q.y + w2[4] * q.z;
        float m5 = p45.y + xrB.y + w0[5] * q.x + w1[5] * q.y + w2[5] * q.z;
        float m6 = p67.x + xrB.z + w0[6] * q.x + w1[6] * q.y + w2[6] * q.z;
        float m7 = p67.y + xrB.w + w0[7] * q.x + w1[7] * q.y + w2[7] * q.z;
        m0 = (m0 > 0.f) ? m0 : 0.2f * m0;
        m1 = (m1 > 0.f) ? m1 : 0.2f * m1;
        m2 = (m2 > 0.f) ? m2 : 0.2f * m2;
        m3 = (m3 > 0.f) ? m3 : 0.2f * m3;
        m4 = (m4 > 0.f) ? m4 : 0.2f * m4;
        m5 = (m5 > 0.f) ? m5 : 0.2f * m5;
        m6 = (m6 > 0.f) ? m6 : 0.2f * m6;
        m7 = (m7 > 0.f) ? m7 : 0.2f * m7;
        float part = m0 * aA.x + m1 * aA.y + m2 * aA.z + m3 * aA.w
                   + m4 * aB.x + m5 * aB.y + m6 * aB.z + m7 * aB.w;
        part += __shfl_xor_sync(hm, part, 1);
        part += __shfl_xor_sync(hm, part, 2);   // head score (4-lane group)
        float pe = __expf(part);
        den += pe;
        accA.x += pe * p01.x; accA.y += pe * p01.y;
        accA.z += pe * p23.x; accA.w += pe * p23.y;
        accB.x += pe * p45.x; accB.y += pe * p45.y;
        accB.z += pe * p67.x; accB.w += pe * p67.y;
    }
    // self-loop: attr = mean of incoming real-edge attrs, src = v
    {
        float cinv = 1.f / fmaxf((float)(pend - pbeg), 1.f);
        float e0 = se0 * cinv, e1 = se1 * cinv, e2 = se2 * cinv;
        uint4 raw = *(const uint4*)(g_xl1h + (long)v * 64 + 4 * ln);
        float2 p01 = __bfloat1622float2(*(__nv_bfloat162*)&raw.x);
        float2 p23 = __bfloat1622float2(*(__nv_bfloat162*)&raw.y);
        float2 p45 = __bfloat1622float2(*(__nv_bfloat162*)&raw.z);
        float2 p67 = __bfloat1622float2(*(__nv_bfloat162*)&raw.w);
        float m0 = p01.x + xrA.x + w0[0] * e0 + w1[0] * e1 + w2[0] * e2;
        float m1 = p01.y + xrA.y + w0[1] * e0 + w1[1] * e1 + w2[1] * e2;
        float m2 = p23.x + xrA.z + w0[2] * e0 + w1[2] * e1 + w2[2] * e2;
        float m3 = p23.y + xrA.w + w0[3] * e0 + w1[3] * e1 + w2[3] * e2;
        float m4 = p45.x + xrB.x + w0[4] * e0 + w1[4] * e1 + w2[4] * e2;
        float m5 = p45.y + xrB.y + w0[5] * e0 + w1[5] * e1 + w2[5] * e2;
        float m6 = p67.x + xrB.z + w0[6] * e0 + w1[6] * e1 + w2[6] * e2;
        float m7 = p67.y + xrB.w + w0[7] * e0 + w1[7] * e1 + w2[7] * e2;
        m0 = (m0 > 0.f) ? m0 : 0.2f * m0;
        m1 = (m1 > 0.f) ? m1 : 0.2f * m1;
        m2 = (m2 > 0.f) ? m2 : 0.2f * m2;
        m3 = (m3 > 0.f) ? m3 : 0.2f * m3;
        m4 = (m4 > 0.f) ? m4 : 0.2f * m4;
        m5 = (m5 > 0.f) ? m5 : 0.2f * m5;
        m6 = (m6 > 0.f) ? m6 : 0.2f * m6;
        m7 = (m7 > 0.f) ? m7 : 0.2f * m7;
        float part = m0 * aA.x + m1 * aA.y + m2 * aA.z + m3 * aA.w
                   + m4 * aB.x + m5 * aB.y + m6 * aB.z + m7 * aB.w;
        part += __shfl_xor_sync(hm, part, 1);
        part += __shfl_xor_sync(hm, part, 2);
        float pe = __expf(part);
        den += pe;
        accA.x += pe * p01.x; accA.y += pe * p01.y;
        accA.z += pe * p23.x; accA.w += pe * p23.y;
        accB.x += pe * p45.x; accB.y += pe * p45.y;
        accB.z += pe * p67.x; accB.w += pe * p67.y;
    }
    float4 bA = *(const float4*)&bias[cb];
    float4 bB = *(const float4*)&bias[cb + 4];
    float inv = 1.f / den;
    float4 oA, oB;
    oA.x = accA.x * inv + bA.x;  oA.y = accA.y * inv + bA.y;
    oA.z = accA.z * inv + bA.z;  oA.w = accA.w * inv + bA.w;
    oB.x = accB.x * inv + bB.x;  oB.y = accB.y * inv + bB.y;
    oB.z = accB.z * inv + bB.z;  oB.w = accB.w * inv + bB.w;
    oA.x = (oA.x > 0.f) ? oA.x : (__expf(oA.x) - 1.f);
    oA.y = (oA.y > 0.f) ? oA.y : (__expf(oA.y) - 1.f);
    oA.z = (oA.z > 0.f) ? oA.z : (__expf(oA.z) - 1.f);
    oA.w = (oA.w > 0.f) ? oA.w : (__expf(oA.w) - 1.f);
    oB.x = (oB.x > 0.f) ? oB.x : (__expf(oB.x) - 1.f);
    oB.y = (oB.y > 0.f) ? oB.y : (__expf(oB.y) - 1.f);
    oB.z = (oB.z > 0.f) ? oB.z : (__expf(oB.z) - 1.f);
    oB.w = (oB.w > 0.f) ? oB.w : (__expf(oB.w) - 1.f);
    *(float4*)&g_h1[(long)v * 128 + cb]     = oA;
    *(float4*)&g_h1[(long)v * 128 + cb + 4] = oB;
}

// ---------------- GATv2 layer 2 + fused pooling: HALF-warp per node --------
// 16 lanes/node; lane owns 4 channels; 4-shfl masked reduce.
__global__ void k_gat2(const float* __restrict__ We, const float* __restrict__ att,
                       const float* __restrict__ bias, const int* __restrict__ batch) {
    int gw = (blockIdx.x * blockDim.x + threadIdx.x) >> 5;
    int lane = threadIdx.x & 31;
    int half = lane >> 4, ln = lane & 15;
    int v = 2 * gw + half;
    if (v >= NN) return;
    unsigned hm = half ? 0xFFFF0000u : 0x0000FFFFu;
    int c0 = 4 * ln;
    float4 a4 = *(const float4*)&att[c0];
    float w0[4], w1[4], w2[4];
#pragma unroll
    for (int j = 0; j < 4; j++) {
        w0[j] = We[(c0 + j) * 3 + 0];
        w1[j] = We[(c0 + j) * 3 + 1];
        w2[j] = We[(c0 + j) * 3 + 2];
    }
    float4 xr = *(const float4*)&g_xr2[(long)v * 64 + c0];
    float den = 0.f;
    float4 acc = make_float4(0.f, 0.f, 0.f, 0.f);
    int pbeg = g_rowptr[v], pend = g_rowptr[v + 1];
    float se0 = 0.f, se1 = 0.f, se2 = 0.f;
#pragma unroll 2
    for (int p = pbeg; p < pend; ++p) {
        float4 q = g_edge[p];
        int s = __float_as_int(q.w);
        se0 += q.x; se1 += q.y; se2 += q.z;
        uint2 raw = *(const uint2*)(g_xl2h + (long)s * 32 + 2 * ln);
        float2 p01 = __bfloat1622float2(*(__nv_bfloat162*)&raw.x);
        float2 p23 = __bfloat1622float2(*(__nv_bfloat162*)&raw.y);
        float m0 = p01.x + xr.x + w0[0] * q.x + w1[0] * q.y + w2[0] * q.z;
        float m1 = p01.y + xr.y + w0[1] * q.x + w1[1] * q.y + w2[1] * q.z;
        float m2 = p23.x + xr.z + w0[2] * q.x + w1[2] * q.y + w2[2] * q.z;
        float m3 = p23.y + xr.w + w0[3] * q.x + w1[3] * q.y + w2[3] * q.z;
        m0 = (m0 > 0.f) ? m0 : 0.2f * m0;
        m1 = (m1 > 0.f) ? m1 : 0.2f * m1;
        m2 = (m2 > 0.f) ? m2 : 0.2f * m2;
        m3 = (m3 > 0.f) ? m3 : 0.2f * m3;
        float sc = m0 * a4.x + m1 * a4.y + m2 * a4.z + m3 * a4.w;
        sc += __shfl_xor_sync(hm, sc, 8);
        sc += __shfl_xor_sync(hm, sc, 4);
        sc += __shfl_xor_sync(hm, sc, 2);
        sc += __shfl_xor_sync(hm, sc, 1);
        float pe = __expf(sc);
        den += pe;
        acc.x += pe * p01.x; acc.y += pe * p01.y;
        acc.z += pe * p23.x; acc.w += pe * p23.y;
    }
    // self-loop
    {
        float cinv = 1.f / fmaxf((float)(pend - pbeg), 1.f);
        float e0 = se0 * cinv, e1 = se1 * cinv, e2 = se2 * cinv;
        uint2 raw = *(const uint2*)(g_xl2h + (long)v * 32 + 2 * ln);
        float2 p01 = __bfloat1622float2(*(__nv_bfloat162*)&raw.x);
        float2 p23 = __bfloat1622float2(*(__nv_bfloat162*)&raw.y);
        float m0 = p01.x + xr.x + w0[0] * e0 + w1[0] * e1 + w2[0] * e2;
        float m1 = p01.y + xr.y + w0[1] * e0 + w1[1] * e1 + w2[1] * e2;
        float m2 = p23.x + xr.z + w0[2] * e0 + w1[2] * e1 + w2[2] * e2;
        float m3 = p23.y + xr.w + w0[3] * e0 + w1[3] * e1 + w2[3] * e2;
        m0 = (m0 > 0.f) ? m0 : 0.2f * m0;
        m1 = (m1 > 0.f) ? m1 : 0.2f * m1;
        m2 = (m2 > 0.f) ? m2 : 0.2f * m2;
        m3 = (m3 > 0.f) ? m3 : 0.2f * m3;
        float sc = m0 * a4.x + m1 * a4.y + m2 * a4.z + m3 * a4.w;
        sc += __shfl_xor_sync(hm, sc, 8);
        sc += __shfl_xor_sync(hm, sc, 4);
        sc += __shfl_xor_sync(hm, sc, 2);
        sc += __shfl_xor_sync(hm, sc, 1);
        float pe = __expf(sc);
        den += pe;
        acc.x += pe * p01.x; acc.y += pe * p01.y;
        acc.z += pe * p23.x; acc.w += pe * p23.y;
    }
    float4 b4 = *(const float4*)&bias[c0];
    float inv = 1.f / den;
    float o0 = acc.x * inv + b4.x;
    float o1 = acc.y * inv + b4.y;
    float o2 = acc.z * inv + b4.z;
    float o3 = acc.w * inv + b4.w;
    o0 = (o0 > 0.f) ? o0 : (__expf(o0) - 1.f);
    o1 = (o1 > 0.f) ? o1 : (__expf(o1) - 1.f);
    o2 = (o2 > 0.f) ? o2 : (__expf(o2) - 1.f);
    o3 = (o3 > 0.f) ? o3 : (__expf(o3) - 1.f);
    int b = batch[v];
    atomicAdd(&g_pooled[b * 64 + c0 + 0], o0);
    atomicAdd(&g_pooled[b * 64 + c0 + 1], o1);
    atomicAdd(&g_pooled[b * 64 + c0 + 2], o2);
    atomicAdd(&g_pooled[b * 64 + c0 + 3], o3);
    if (ln == 0) atomicAdd(&g_gcnt[b], 1);
}

// ---------------- head MLP: block per graph; self-cleans pooled/gcnt -------
__global__ void k_head(const float* __restrict__ u,
                       const float* __restrict__ Wl, const float* __restrict__ bl,
                       const float* __restrict__ Wh, const float* __restrict__ bh,
                       float* __restrict__ out) {
    int g = blockIdx.x;
    __shared__ float pm[64];
    __shared__ float z[32];
    int t = threadIdx.x;   // 64 threads
    float c = fmaxf((float)g_gcnt[g], 1.f);
    pm[t] = g_pooled[g * 64 + t] / c;
    g_pooled[g * 64 + t] = 0.f;        // self-clean for the next run
    __syncthreads();
    if (t == 0) g_gcnt[g] = 0;         // after all threads read c
    if (t < 32) {
        float s = bl[t];
#pragma unroll
        for (int k = 0; k < 64; k++) s += pm[k] * Wl[t * 65 + k];
        s += u[g] * Wl[t * 65 + 64];
        z[t] = fmaxf(s, 0.f);
    }
    __syncthreads();
    if (t < 10) {
        float s = bh[t];
#pragma unroll
        for (int j = 0; j < 32; j++) s += z[j] * Wh[t * 32 + j];
        out[g * 10 + t] = s;
    }
}

// ---------------- launch ----------------------------------------------------
extern "C" void kernel_launch(void* const* d_in, const int* in_sizes, int n_in,
                              void* d_out, int out_size) {
    const float* x     = (const float*)d_in[0];
    const int*   ei    = (const int*)d_in[1];
    const float* ea    = (const float*)d_in[2];
    const int*   batch = (const int*)d_in[3];
    const float* u     = (const float*)d_in[4];
    const float* Wl1   = (const float*)d_in[5];
    const float* bl1   = (const float*)d_in[6];
    const float* Wr1   = (const float*)d_in[7];
    const float* br1   = (const float*)d_in[8];
    const float* We1   = (const float*)d_in[9];
    const float* att1  = (const float*)d_in[10];
    const float* b1    = (const float*)d_in[11];
    const float* Wl2   = (const float*)d_in[12];
    const float* bl2   = (const float*)d_in[13];
    const float* Wr2   = (const float*)d_in[14];
    const float* br2   = (const float*)d_in[15];
    const float* We2   = (const float*)d_in[16];
    const float* att2  = (const float*)d_in[17];
    const float* b2    = (const float*)d_in[18];
    const float* Wlin  = (const float*)d_in[19];
    const float* blin  = (const float*)d_in[20];
    const float* Wh    = (const float*)d_in[21];
    const float* bh    = (const float*)d_in[22];
    float* out = (float*)d_out;

    __nv_bfloat162 *p_xl1h, *p_xl2h;
    float *p_xr1, *p_h1, *p_xr2;
    cudaGetSymbolAddress((void**)&p_xl1h, g_xl1h);
    cudaGetSymbolAddress((void**)&p_xr1,  g_xr1);
    cudaGetSymbolAddress((void**)&p_h1,   g_h1);
    cudaGetSymbolAddress((void**)&p_xl2h, g_xl2h);
    cudaGetSymbolAddress((void**)&p_xr2,  g_xr2);

    // fork: GEMM1 (needs only x) runs concurrently with the CSR build
    cudaStream_t side;
    cudaStreamCreateWithFlags(&side, cudaStreamNonBlocking);
    cudaEvent_t evFork, evJoin;
    cudaEventCreateWithFlags(&evFork, cudaEventDisableTiming);
    cudaEventCreateWithFlags(&evJoin, cudaEventDisableTiming);

    cudaEventRecord(evFork, 0);
    cudaStreamWaitEvent(side, evFork, 0);
    dim3 g1(2, (NN + 127) / 128, 2);
    gemm_tf32<<<g1, 256, 0, side>>>(x, Wl1, Wr1, bl1, br1, p_xl1h, p_xr1, NN, 128);
    cudaEventRecord(evJoin, side);

    k_degree<<<(EE + 255) / 256, 256>>>(ei);
    k_scan1<<<64, 256>>>();
    k_scan3<<<64, 256>>>();
    k_scatter<<<(EE + 255) / 256, 256>>>(ei, ea);

    cudaStreamWaitEvent(0, evJoin, 0);
    // half-warp per node: NN/2 warps
    k_gat1<<<(NN / 2 + 7) / 8, 256>>>(We1, att1, b1);

    dim3 g2(1, (NN + 127) / 128, 2);
    gemm_tf32<<<g2, 256>>>(p_h1, Wl2, Wr2, bl2, br2, p_xl2h, p_xr2, NN, 64);

    k_gat2<<<(NN / 2 + 7) / 8, 256>>>(We2, att2, b2, batch);

    k_head<<<GG, 64>>>(u, Wlin, blin, Wh, bh, out);

    cudaEventDestroy(evFork);
    cudaEventDestroy(evJoin);
    cudaStreamDestroy(side);
}

// round 17
// speedup vs baseline: 1.0088x; 1.0088x over previous
#include <cuda_runtime.h>
#include <cuda_bf16.h>
#include <math.h>

#define NN   50000
#define EE   800000
#define GG   512
#define NHALF 25000

// ---------------- scratch (static device globals; no allocation allowed) ----
// All accumulating arrays are zeroed by their LAST consumer each run.
__device__ int    g_cnt[NN];
__device__ int    g_rowptr[NN + 1];
__device__ int    g_cursor[NN];
__device__ uint2  g_edge[EE];          // {bf16 e0|e1, bf16 e2 | src<<16} CSR-by-dst
__device__ __nv_bfloat162 g_xl1h[NN * 64];  // xl1 bf16x2 (gathered per edge)
__device__ float  g_xr1[NN * 128];
__device__ float  g_h1[NN * 128];
__device__ __nv_bfloat162 g_xl2h[NN * 32];  // xl2 bf16x2 (gathered per edge)
__device__ float  g_xr2[NN * 64];
__device__ float  g_pooled[GG * 64];
__device__ int    g_gcnt[GG];
__device__ int    g_bsum[64];

// ---------------- in-degree (int atomics only) -----------------------------
__global__ void k_degree(const int* __restrict__ ei) {
    int e = blockIdx.x * blockDim.x + threadIdx.x;
    if (e >= EE) return;
    atomicAdd(&g_cnt[ei[EE + e]], 1);
}

// ---------------- 2-phase multi-block exclusive scan of deg ----------------
__global__ void k_scan1() {
    __shared__ int red[256];
    int t = threadIdx.x, b = blockIdx.x;
    int g = b * 256 + t;
    int s = 0;
#pragma unroll
    for (int i = 0; i < 4; i++) {
        int v = g * 4 + i;
        if (v < NN) s += g_cnt[v];
    }
    red[t] = s;
    __syncthreads();
    for (int off = 128; off > 0; off >>= 1) {
        if (t < off) red[t] += red[t + off];
        __syncthreads();
    }
    if (t == 0) g_bsum[b] = red[0];
}

__global__ void k_scan3() {
    __shared__ int wsum[8];
    __shared__ int boff_s;
    int t = threadIdx.x, b = blockIdx.x;
    int lane = t & 31, warp = t >> 5;
    if (t == 0) {
        int r = 0;
        for (int i = 0; i < b; i++) r += g_bsum[i];
        boff_s = r;
    }
    int g = b * 256 + t;
    int vals[4];
    int tot = 0;
#pragma unroll
    for (int i = 0; i < 4; i++) {
        int v = g * 4 + i;
        vals[i] = (v < NN) ? g_cnt[v] : 0;
        tot += vals[i];
    }
    int inc = tot;
#pragma unroll
    for (int off = 1; off < 32; off <<= 1) {
        int n = __shfl_up_sync(0xffffffffu, inc, off);
        if (lane >= off) inc += n;
    }
    if (lane == 31) wsum[warp] = inc;
    __syncthreads();
    if (t == 0) {
        int r = 0;
        for (int w = 0; w < 8; w++) { int x = wsum[w]; wsum[w] = r; r += x; }
    }
    __syncthreads();
    int run = boff_s + wsum[warp] + inc - tot;
#pragma unroll
    for (int i = 0; i < 4; i++) {
        int v = g * 4 + i;
        if (v < NN) {
            g_rowptr[v] = run;
            g_cursor[v] = run;       // scatter bumps this directly
            g_cnt[v] = 0;            // self-clean
            run += vals[i];
            if (v == NN - 1) g_rowptr[NN] = run;
        }
    }
}

// ---------------- scatter edges (packed 8B) into CSR-by-dst ----------------
__global__ void k_scatter(const int* __restrict__ ei, const float* __restrict__ ea) {
    int e = blockIdx.x * blockDim.x + threadIdx.x;
    if (e >= EE) return;
    int s = ei[e], d = ei[EE + e];
    int pos = atomicAdd(&g_cursor[d], 1);
    __nv_bfloat162 e01 = __floats2bfloat162_rn(ea[e * 3 + 0], ea[e * 3 + 1]);
    unsigned short e2b = __bfloat16_as_ushort(__float2bfloat16_rn(ea[e * 3 + 2]));
    uint2 q;
    q.x = *(unsigned*)&e01;
    q.y = (unsigned)e2b | ((unsigned)s << 16);
    g_edge[pos] = q;
}

// ---------------- tf32 tensor-core GEMM (m16n8k4, static 28KB smem) --------
// blockIdx.z==0 -> xl output packed bf16x2; z==1 -> xr fp32.
// Rows covered: [m0 + by*128, ...) clamped to mend.
__device__ __forceinline__ unsigned f2tf32(float f) {
    unsigned r;
    asm("cvt.rna.tf32.f32 %0, %1;" : "=r"(r) : "f"(f));
    return r;
}

__device__ __forceinline__ void mma_k4(float c[4], unsigned a0, unsigned a1, unsigned b0) {
    asm volatile(
        "mma.sync.aligned.m16n8k4.row.col.f32.tf32.tf32.f32 "
        "{%0,%1,%2,%3}, {%4,%5}, {%6}, {%0,%1,%2,%3};"
        : "+f"(c[0]), "+f"(c[1]), "+f"(c[2]), "+f"(c[3])
        : "r"(a0), "r"(a1), "r"(b0));
}

__global__ void gemm_tf32(const float* __restrict__ A,
                          const float* __restrict__ W0, const float* __restrict__ W1,
                          const float* __restrict__ bias0, const float* __restrict__ bias1,
                          __nv_bfloat162* __restrict__ C0h, float* __restrict__ C1,
                          int m0, int mend, int Ncol) {
    __shared__ unsigned Bh[64][36];
    __shared__ unsigned As[128][36];

    const float* W    = blockIdx.z ? W1 : W0;
    const float* bias = blockIdx.z ? bias1 : bias0;

    int tid = threadIdx.x;
    int lane = tid & 31, warp = tid >> 5;
    int bm = m0 + blockIdx.y * 128;
    int bn = blockIdx.x * 64;
    int wm = (warp & 3) * 32;
    int wn = (warp >> 2) * 32;
    int lr = lane >> 2;
    int lc = lane & 3;

    float c[2][4][4] = {};

    for (int k0 = 0; k0 < 128; k0 += 32) {
#pragma unroll
        for (int i = 0; i < 2; i++) {
            int idx = tid + i * 256;
            int n = idx >> 3;
            int c4 = (idx & 7) * 4;
            float4 wv = *(const float4*)&W[(size_t)(bn + n) * 128 + k0 + c4];
            Bh[n][c4 + 0] = f2tf32(wv.x);
            Bh[n][c4 + 1] = f2tf32(wv.y);
            Bh[n][c4 + 2] = f2tf32(wv.z);
            Bh[n][c4 + 3] = f2tf32(wv.w);
        }
#pragma unroll
        for (int i = 0; i < 4; i++) {
            int idx = tid + i * 256;
            int r = idx >> 3;
            int c4 = (idx & 7) * 4;
            float4 av = make_float4(0.f, 0.f, 0.f, 0.f);
            if (bm + r < mend) av = *(const float4*)&A[(size_t)(bm + r) * 128 + k0 + c4];
            As[r][c4 + 0] = f2tf32(av.x);
            As[r][c4 + 1] = f2tf32(av.y);
            As[r][c4 + 2] = f2tf32(av.z);
            As[r][c4 + 3] = f2tf32(av.w);
        }
        __syncthreads();

#pragma unroll
        for (int kk = 0; kk < 32; kk += 4) {
            unsigned a0[2], a1[2], bh[4];
#pragma unroll
            for (int mt = 0; mt < 2; mt++) {
                int row = wm + mt * 16 + lr;
                a0[mt] = As[row][kk + lc];
                a1[mt] = As[row + 8][kk + lc];
            }
#pragma unroll
            for (int nt = 0; nt < 4; nt++) {
                int n = wn + nt * 8 + lr;
                bh[nt] = Bh[n][kk + lc];
            }
#pragma unroll
            for (int mt = 0; mt < 2; mt++)
#pragma unroll
                for (int nt = 0; nt < 4; nt++)
                    mma_k4(c[mt][nt], a0[mt], a1[mt], bh[nt]);
        }
        __syncthreads();
    }

    int half = Ncol >> 1;
#pragma unroll
    for (int mt = 0; mt < 2; mt++) {
#pragma unroll
        for (int nt = 0; nt < 4; nt++) {
            int r0 = bm + wm + mt * 16 + lr;
            int cc = bn + wn + nt * 8 + lc * 2;     // always even
            float b0v = bias[cc], b1v = bias[cc + 1];
            if (blockIdx.z == 0) {
                if (r0 < mend)
                    C0h[(size_t)r0 * half + (cc >> 1)] =
                        __floats2bfloat162_rn(c[mt][nt][0] + b0v, c[mt][nt][1] + b1v);
                if (r0 + 8 < mend)
                    C0h[(size_t)(r0 + 8) * half + (cc >> 1)] =
                        __floats2bfloat162_rn(c[mt][nt][2] + b0v, c[mt][nt][3] + b1v);
            } else {
                if (r0 < mend) {
                    C1[(size_t)r0 * Ncol + cc]     = c[mt][nt][0] + b0v;
                    C1[(size_t)r0 * Ncol + cc + 1] = c[mt][nt][1] + b1v;
                }
                if (r0 + 8 < mend) {
                    C1[(size_t)(r0 + 8) * Ncol + cc]     = c[mt][nt][2] + b0v;
                    C1[(size_t)(r0 + 8) * Ncol + cc + 1] = c[mt][nt][3] + b1v;
                }
            }
        }
    }
}

// ---------------- GATv2 layer 1: warp/node; lane owns 4 channels -----------
// R15-proven body: exp-sum softmax, independent loads, unroll 2.
// Node range [vbase, vend) for the gat1 / GEMM2 pipeline split.
__global__ void k_gat1(const float* __restrict__ We, const float* __restrict__ att,
                       const float* __restrict__ bias, int vbase, int vend) {
    int gw = (blockIdx.x * blockDim.x + threadIdx.x) >> 5;
    int lane = threadIdx.x & 31;
    int v = vbase + gw;
    if (v >= vend) return;
    int cb = 4 * lane;
    float4 a4 = *(const float4*)&att[cb];
    float w0[4], w1[4], w2[4];
#pragma unroll
    for (int j = 0; j < 4; j++) {
        w0[j] = We[(cb + j) * 3 + 0];
        w1[j] = We[(cb + j) * 3 + 1];
        w2[j] = We[(cb + j) * 3 + 2];
    }
    float4 xr = *(const float4*)&g_xr1[(long)v * 128 + cb];
    float den = 0.f;
    float4 acc = make_float4(0.f, 0.f, 0.f, 0.f);
    int pbeg = g_rowptr[v], pend = g_rowptr[v + 1];
    float se0 = 0.f, se1 = 0.f, se2 = 0.f;
#pragma unroll 2
    for (int p = pbeg; p < pend; ++p) {
        uint2 qp = g_edge[p];
        float2 e01 = __bfloat1622float2(*(__nv_bfloat162*)&qp.x);
        float e2 = __bfloat162float(__ushort_as_bfloat16((unsigned short)(qp.y & 0xffffu)));
        int s = (int)(qp.y >> 16);
        se0 += e01.x; se1 += e01.y; se2 += e2;
        uint2 raw = *(const uint2*)(g_xl1h + (long)s * 64 + 2 * lane);
        float2 p01 = __bfloat1622float2(*(__nv_bfloat162*)&raw.x);
        float2 p23 = __bfloat1622float2(*(__nv_bfloat162*)&raw.y);
        float m0 = p01.x + xr.x + w0[0] * e01.x + w1[0] * e01.y + w2[0] * e2;
        float m1 = p01.y + xr.y + w0[1] * e01.x + w1[1] * e01.y + w2[1] * e2;
        float m2 = p23.x + xr.z + w0[2] * e01.x + w1[2] * e01.y + w2[2] * e2;
        float m3 = p23.y + xr.w + w0[3] * e01.x + w1[3] * e01.y + w2[3] * e2;
        m0 = (m0 > 0.f) ? m0 : 0.2f * m0;
        m1 = (m1 > 0.f) ? m1 : 0.2f * m1;
        m2 = (m2 > 0.f) ? m2 : 0.2f * m2;
        m3 = (m3 > 0.f) ? m3 : 0.2f * m3;
        float part = m0 * a4.x + m1 * a4.y + m2 * a4.z + m3 * a4.w;
        part += __shfl_xor_sync(0xffffffffu, part, 1);
        part += __shfl_xor_sync(0xffffffffu, part, 2);
        part += __shfl_xor_sync(0xffffffffu, part, 4);
        float pe = __expf(part);
        den += pe;
        acc.x += pe * p01.x;
        acc.y += pe * p01.y;
        acc.z += pe * p23.x;
        acc.w += pe * p23.y;
    }
    // self-loop: attr = mean of incoming real-edge attrs, src = v
    {
        float cinv = 1.f / fmaxf((float)(pend - pbeg), 1.f);
        float e0 = se0 * cinv, e1 = se1 * cinv, e2 = se2 * cinv;
        uint2 raw = *(const uint2*)(g_xl1h + (long)v * 64 + 2 * lane);
        float2 p01 = __bfloat1622float2(*(__nv_bfloat162*)&raw.x);
        float2 p23 = __bfloat1622float2(*(__nv_bfloat162*)&raw.y);
        float m0 = p01.x + xr.x + w0[0] * e0 + w1[0] * e1 + w2[0] * e2;
        float m1 = p01.y + xr.y + w0[1] * e0 + w1[1] * e1 + w2[1] * e2;
        float m2 = p23.x + xr.z + w0[2] * e0 + w1[2] * e1 + w2[2] * e2;
        float m3 = p23.y + xr.w + w0[3] * e0 + w1[3] * e1 + w2[3] * e2;
        m0 = (m0 > 0.f) ? m0 : 0.2f * m0;
        m1 = (m1 > 0.f) ? m1 : 0.2f * m1;
        m2 = (m2 > 0.f) ? m2 : 0.2f * m2;
        m3 = (m3 > 0.f) ? m3 : 0.2f * m3;
        float part = m0 * a4.x + m1 * a4.y + m2 * a4.z + m3 * a4.w;
        part += __shfl_xor_sync(0xffffffffu, part, 1);
        part += __shfl_xor_sync(0xffffffffu, part, 2);
        part += __shfl_xor_sync(0xffffffffu, part, 4);
        float pe = __expf(part);
        den += pe;
        acc.x += pe * p01.x;
        acc.y += pe * p01.y;
        acc.z += pe * p23.x;
        acc.w += pe * p23.y;
    }
    float4 b4 = *(const float4*)&bias[cb];
    float inv = 1.f / den;
    float4 o;
    o.x = acc.x * inv + b4.x;
    o.y = acc.y * inv + b4.y;
    o.z = acc.z * inv + b4.z;
    o.w = acc.w * inv + b4.w;
    o.x = (o.x > 0.f) ? o.x : (__expf(o.x) - 1.f);
    o.y = (o.y > 0.f) ? o.y : (__expf(o.y) - 1.f);
    o.z = (o.z > 0.f) ? o.z : (__expf(o.z) - 1.f);
    o.w = (o.w > 0.f) ? o.w : (__expf(o.w) - 1.f);
    *(float4*)&g_h1[(long)v * 128 + cb] = o;
}

// ---------------- GATv2 layer 2 + fused mean pooling; lane owns 2 channels --
__global__ void k_gat2(const float* __restrict__ We, const float* __restrict__ att,
                       const float* __restrict__ bias, const int* __restrict__ batch) {
    int gw = (blockIdx.x * blockDim.x + threadIdx.x) >> 5;
    int lane = threadIdx.x & 31;
    if (gw >= NN) return;
    int v = gw;
    int c0 = 2 * lane, c1 = 2 * lane + 1;
    float aa = att[c0], ab = att[c1];
    float wa0 = We[c0 * 3 + 0], wa1 = We[c0 * 3 + 1], wa2 = We[c0 * 3 + 2];
    float wb0 = We[c1 * 3 + 0], wb1 = We[c1 * 3 + 1], wb2 = We[c1 * 3 + 2];
    float2 xr = *(const float2*)&g_xr2[(long)v * 64 + c0];
    float den = 0.f, acca = 0.f, accb = 0.f;
    int pbeg = g_rowptr[v], pend = g_rowptr[v + 1];
    float se0 = 0.f, se1 = 0.f, se2 = 0.f;
#pragma unroll 2
    for (int p = pbeg; p < pend; ++p) {
        uint2 qp = g_edge[p];
        float2 e01 = __bfloat1622float2(*(__nv_bfloat162*)&qp.x);
        float e2 = __bfloat162float(__ushort_as_bfloat16((unsigned short)(qp.y & 0xffffu)));
        int s = (int)(qp.y >> 16);
        se0 += e01.x; se1 += e01.y; se2 += e2;
        float2 xl = __bfloat1622float2(g_xl2h[(long)s * 32 + lane]);
        float ma = xl.x + xr.x + wa0 * e01.x + wa1 * e01.y + wa2 * e2;
        float mb = xl.y + xr.y + wb0 * e01.x + wb1 * e01.y + wb2 * e2;
        ma = (ma > 0.f) ? ma : 0.2f * ma;
        mb = (mb > 0.f) ? mb : 0.2f * mb;
        float sc = ma * aa + mb * ab;
#pragma unroll
        for (int off = 16; off > 0; off >>= 1)
            sc += __shfl_xor_sync(0xffffffffu, sc, off);
        float pe = __expf(sc);
        den += pe;
        acca += pe * xl.x;
        accb += pe * xl.y;
    }
    // self-loop
    {
        float cinv = 1.f / fmaxf((float)(pend - pbeg), 1.f);
        float e0 = se0 * cinv, e1 = se1 * cinv, e2 = se2 * cinv;
        float2 xl = __bfloat1622float2(g_xl2h[(long)v * 32 + lane]);
        float ma = xl.x + xr.x + wa0 * e0 + wa1 * e1 + wa2 * e2;
        float mb = xl.y + xr.y + wb0 * e0 + wb1 * e1 + wb2 * e2;
        ma = (ma > 0.f) ? ma : 0.2f * ma;
        mb = (mb > 0.f) ? mb : 0.2f * mb;
        float sc = ma * aa + mb * ab;
#pragma unroll
        for (int off = 16; off > 0; off >>= 1)
            sc += __shfl_xor_sync(0xffffffffu, sc, off);
        float pe = __expf(sc);
        den += pe;
        acca += pe * xl.x;
        accb += pe * xl.y;
    }
    float oa = acca / den + bias[c0];
    float ob = accb / den + bias[c1];
    oa = (oa > 0.f) ? oa : (__expf(oa) - 1.f);
    ob = (ob > 0.f) ? ob : (__expf(ob) - 1.f);
    int b = batch[v];
    atomicAdd(&g_pooled[b * 64 + c0], oa);
    atomicAdd(&g_pooled[b * 64 + c1], ob);
    if (lane == 0) atomicAdd(&g_gcnt[b], 1);
}

// ---------------- head MLP: block per graph; self-cleans pooled/gcnt -------
__global__ void k_head(const float* __restrict__ u,
                       const float* __restrict__ Wl, const float* __restrict__ bl,
                       const float* __restrict__ Wh, const float* __restrict__ bh,
                       float* __restrict__ out) {
    int g = blockIdx.x;
    __shared__ float pm[64];
    __shared__ float z[32];
    int t = threadIdx.x;   // 64 threads
    float c = fmaxf((float)g_gcnt[g], 1.f);
    pm[t] = g_pooled[g * 64 + t] / c;
    g_pooled[g * 64 + t] = 0.f;        // self-clean
    __syncthreads();
    if (t == 0) g_gcnt[g] = 0;
    if (t < 32) {
        float s = bl[t];
#pragma unroll
        for (int k = 0; k < 64; k++) s += pm[k] * Wl[t * 65 + k];
        s += u[g] * Wl[t * 65 + 64];
        z[t] = fmaxf(s, 0.f);
    }
    __syncthreads();
    if (t < 10) {
        float s = bh[t];
#pragma unroll
        for (int j = 0; j < 32; j++) s += z[j] * Wh[t * 32 + j];
        out[g * 10 + t] = s;
    }
}

// ---------------- launch ----------------------------------------------------
extern "C" void kernel_launch(void* const* d_in, const int* in_sizes, int n_in,
                              void* d_out, int out_size) {
    const float* x     = (const float*)d_in[0];
    const int*   ei    = (const int*)d_in[1];
    const float* ea    = (const float*)d_in[2];
    const int*   batch = (const int*)d_in[3];
    const float* u     = (const float*)d_in[4];
    const float* Wl1   = (const float*)d_in[5];
    const float* bl1   = (const float*)d_in[6];
    const float* Wr1   = (const float*)d_in[7];
    const float* br1   = (const float*)d_in[8];
    const float* We1   = (const float*)d_in[9];
    const float* att1  = (const float*)d_in[10];
    const float* b1    = (const float*)d_in[11];
    const float* Wl2   = (const float*)d_in[12];
    const float* bl2   = (const float*)d_in[13];
    const float* Wr2   = (const float*)d_in[14];
    const float* br2   = (const float*)d_in[15];
    const float* We2   = (const float*)d_in[16];
    const float* att2  = (const float*)d_in[17];
    const float* b2    = (const float*)d_in[18];
    const float* Wlin  = (const float*)d_in[19];
    const float* blin  = (const float*)d_in[20];
    const float* Wh    = (const float*)d_in[21];
    const float* bh    = (const float*)d_in[22];
    float* out = (float*)d_out;

    __nv_bfloat162 *p_xl1h, *p_xl2h;
    float *p_xr1, *p_h1, *p_xr2;
    cudaGetSymbolAddress((void**)&p_xl1h, g_xl1h);
    cudaGetSymbolAddress((void**)&p_xr1,  g_xr1);
    cudaGetSymbolAddress((void**)&p_h1,   g_h1);
    cudaGetSymbolAddress((void**)&p_xl2h, g_xl2h);
    cudaGetSymbolAddress((void**)&p_xr2,  g_xr2);

    cudaStream_t side;
    cudaStreamCreateWithFlags(&side, cudaStreamNonBlocking);
    cudaEvent_t evFork, evJoin, evA, evG2a;
    cudaEventCreateWithFlags(&evFork, cudaEventDisableTiming);
    cudaEventCreateWithFlags(&evJoin, cudaEventDisableTiming);
    cudaEventCreateWithFlags(&evA,    cudaEventDisableTiming);
    cudaEventCreateWithFlags(&evG2a,  cudaEventDisableTiming);

    // fork: GEMM1 (needs only x) runs concurrently with the CSR build
    cudaEventRecord(evFork, 0);
    cudaStreamWaitEvent(side, evFork, 0);
    dim3 g1(2, (NN + 127) / 128, 2);
    gemm_tf32<<<g1, 256, 0, side>>>(x, Wl1, Wr1, bl1, br1, p_xl1h, p_xr1, 0, NN, 128);
    cudaEventRecord(evJoin, side);

    k_degree<<<(EE + 255) / 256, 256>>>(ei);
    k_scan1<<<64, 256>>>();
    k_scan3<<<64, 256>>>();
    k_scatter<<<(EE + 255) / 256, 256>>>(ei, ea);

    cudaStreamWaitEvent(0, evJoin, 0);
    // gat1 first half; GEMM2 rows [0, NHALF) runs on side overlapped with gat1b
    k_gat1<<<(NHALF + 7) / 8, 256>>>(We1, att1, b1, 0, NHALF);
    cudaEventRecord(evA, 0);
    cudaStreamWaitEvent(side, evA, 0);
    dim3 g2a(1, (NHALF + 127) / 128, 2);
    gemm_tf32<<<g2a, 256, 0, side>>>(p_h1, Wl2, Wr2, bl2, br2, p_xl2h, p_xr2, 0, NHALF, 64);
    cudaEventRecord(evG2a, side);

    k_gat1<<<(NN - NHALF + 7) / 8, 256>>>(We1, att1, b1, NHALF, NN);
    dim3 g2b(1, (NN - NHALF + 127) / 128, 2);
    gemm_tf32<<<g2b, 256>>>(p_h1, Wl2, Wr2, bl2, br2, p_xl2h, p_xr2, NHALF, NN, 64);

    cudaStreamWaitEvent(0, evG2a, 0);
    k_gat2<<<(NN + 7) / 8, 256>>>(We2, att2, b2, batch);

    k_head<<<GG, 64>>>(u, Wlin, blin, Wh, bh, out);

    cudaEventDestroy(evFork);
    cudaEventDestroy(evJoin);
    cudaEventDestroy(evA);
    cudaEventDestroy(evG2a);
    cudaStreamDestroy(side);
}